// round 2
// baseline (speedup 1.0000x reference)
#include <cuda_runtime.h>

#define B_   128
#define NT_  512
#define NC_  512
#define EMB_ 256
#define DKV_ 60
#define DP_  64   // padded head dim

// ---------------- scratch (static device arrays: allocation-free) ----------
__device__ float g_Q[B_*NT_*DP_];   // (b, t, d) row-major, pre-normalized q-hat
__device__ float g_K[B_*DP_*NC_];   // (b, d, c) d-major, pre-normalized k-hat
__device__ float g_V[B_*NC_*DP_];   // (b, c, d) row-major
__device__ float g_qn[B_*NT_];
__device__ float g_kn[B_*NC_];

// ======================= context projection (K,V) ==========================
// one CTA: (b, 64 context rows). 256 threads.
#define CXP 260   // Xs pitch
#define CWP 128   // Ws pitch (64 K cols + 64 V cols, padded)
#define COP 132   // Os pitch
#define CTX_SMEM_BYTES ((64*CXP + 256*CWP + 64 + 64) * 4)

__global__ void __launch_bounds__(256, 1)
proj_ctx_kernel(const int* __restrict__ citems, const float* __restrict__ cvec,
                const float* __restrict__ Acw, const float* __restrict__ Acb,
                const float* __restrict__ Bcw, const float* __restrict__ Bcb)
{
    extern __shared__ float smc[];
    float* Xs  = smc;                 // [64][CXP] row-major (r, k)
    float* Ws  = smc + 64*CXP;        // [256][CWP] k-major (k, j)
    float* nrm = Ws + 256*CWP;        // [64]
    int*   idxs = (int*)(nrm + 64);   // [64]
    float* Os  = smc;                 // [64][COP], overlaps Xs (used after GEMM)

    const int tid = threadIdx.x;
    const int b  = blockIdx.x >> 3;
    const int c0 = (blockIdx.x & 7) << 6;

    const float4 z4 = make_float4(0.f, 0.f, 0.f, 0.f);
    for (int i = tid; i < 256*CWP/4; i += 256) reinterpret_cast<float4*>(Ws)[i] = z4;
    if (tid < 64) idxs[tid] = citems[b*NC_ + c0 + tid];
    __syncthreads();

    // transpose-load Ac -> Ws cols [0,60), Bc -> Ws cols [64,124)
    for (int i = tid; i < 60*64; i += 256) {
        const int j = i % 60, kq = i / 60;
        float4 w = *reinterpret_cast<const float4*>(Acw + j*EMB_ + 4*kq);
        Ws[(4*kq+0)*CWP + j] = w.x;
        Ws[(4*kq+1)*CWP + j] = w.y;
        Ws[(4*kq+2)*CWP + j] = w.z;
        Ws[(4*kq+3)*CWP + j] = w.w;
    }
    for (int i = tid; i < 60*64; i += 256) {
        const int j = i % 60, kq = i / 60;
        float4 w = *reinterpret_cast<const float4*>(Bcw + j*EMB_ + 4*kq);
        Ws[(4*kq+0)*CWP + 64 + j] = w.x;
        Ws[(4*kq+1)*CWP + 64 + j] = w.y;
        Ws[(4*kq+2)*CWP + 64 + j] = w.z;
        Ws[(4*kq+3)*CWP + 64 + j] = w.w;
    }
    // gather embeddings
    for (int i = tid; i < 64*64; i += 256) {
        const int r = i >> 6, seg = i & 63;
        float4 v = *reinterpret_cast<const float4*>(cvec + (size_t)idxs[r]*EMB_ + 4*seg);
        *reinterpret_cast<float4*>(&Xs[r*CXP + 4*seg]) = v;
    }
    __syncthreads();

    // GEMM: Os[64][128] = Xs[64][256] @ Ws[256][128]
    const int tx = tid & 15, ty = tid >> 4;
    float acc[4][8];
    #pragma unroll
    for (int i = 0; i < 4; i++)
        #pragma unroll
        for (int j = 0; j < 8; j++) acc[i][j] = 0.f;

    const float* xr0 = &Xs[(4*ty+0)*CXP];
    const float* xr1 = &Xs[(4*ty+1)*CXP];
    const float* xr2 = &Xs[(4*ty+2)*CXP];
    const float* xr3 = &Xs[(4*ty+3)*CXP];

    #pragma unroll 4
    for (int k = 0; k < 256; k++) {
        float aa[4];
        aa[0] = xr0[k]; aa[1] = xr1[k]; aa[2] = xr2[k]; aa[3] = xr3[k];
        float4 b0 = *reinterpret_cast<const float4*>(&Ws[k*CWP + 8*tx]);
        float4 b1 = *reinterpret_cast<const float4*>(&Ws[k*CWP + 8*tx + 4]);
        float bb[8] = {b0.x, b0.y, b0.z, b0.w, b1.x, b1.y, b1.z, b1.w};
        #pragma unroll
        for (int i = 0; i < 4; i++)
            #pragma unroll
            for (int j = 0; j < 8; j++) acc[i][j] += aa[i]*bb[j];
    }

    // bias
    float bj[8];
    #pragma unroll
    for (int j = 0; j < 8; j++) {
        const int jj = 8*tx + j;
        if (jj < 64) bj[j] = (jj < 60)      ? Acb[jj]      : 0.f;
        else         bj[j] = (jj - 64 < 60) ? Bcb[jj - 64] : 0.f;
    }
    __syncthreads();   // Xs dead, Os may be written
    #pragma unroll
    for (int i = 0; i < 4; i++) {
        float4 o0 = make_float4(acc[i][0]+bj[0], acc[i][1]+bj[1], acc[i][2]+bj[2], acc[i][3]+bj[3]);
        float4 o1 = make_float4(acc[i][4]+bj[4], acc[i][5]+bj[5], acc[i][6]+bj[6], acc[i][7]+bj[7]);
        *reinterpret_cast<float4*>(&Os[(4*ty+i)*COP + 8*tx    ]) = o0;
        *reinterpret_cast<float4*>(&Os[(4*ty+i)*COP + 8*tx + 4]) = o1;
    }
    __syncthreads();

    // K norms over cols [0,64) (pads are exactly zero)
    {
        const int r = tid >> 2, q = tid & 3;
        float ss = 0.f;
        #pragma unroll
        for (int s4 = 0; s4 < 4; s4++) {
            float4 v = *reinterpret_cast<const float4*>(&Os[r*COP + q*16 + 4*s4]);
            ss += v.x*v.x + v.y*v.y + v.z*v.z + v.w*v.w;
        }
        ss += __shfl_xor_sync(0xffffffffu, ss, 1);
        ss += __shfl_xor_sync(0xffffffffu, ss, 2);
        const float kn = sqrtf(ss);
        if (q == 0) {
            g_kn[b*NC_ + c0 + r] = kn;
            nrm[r] = (kn > 0.f) ? 1.f/kn : 0.f;
        }
    }
    __syncthreads();

    // K-hat, d-major
    for (int i = tid; i < 64*64; i += 256) {
        const int j = i >> 6, c = i & 63;
        g_K[((size_t)b*DP_ + j)*NC_ + c0 + c] = Os[c*COP + j] * nrm[c];
    }
    // V, row-major
    for (int i = tid; i < 64*16; i += 256) {
        const int c = i >> 4, seg = i & 15;
        float4 v = *reinterpret_cast<const float4*>(&Os[c*COP + 64 + 4*seg]);
        *reinterpret_cast<float4*>(&g_V[((size_t)b*NC_ + c0 + c)*DP_ + 4*seg]) = v;
    }
}

// ========================= target projection (Q) ===========================
#define TWP 64
#define TOP 68
#define TGT_SMEM_BYTES ((64*CXP + 256*TWP + 64 + 64) * 4)

__global__ void __launch_bounds__(256, 1)
proj_tgt_kernel(const int* __restrict__ titems, const float* __restrict__ tvec,
                const float* __restrict__ Atw, const float* __restrict__ Atb)
{
    extern __shared__ float smt[];
    float* Xs  = smt;
    float* Ws  = smt + 64*CXP;        // [256][TWP]
    float* nrm = Ws + 256*TWP;
    int*   idxs = (int*)(nrm + 64);
    float* Os  = smt;                 // [64][TOP]

    const int tid = threadIdx.x;
    const int b  = blockIdx.x >> 3;
    const int t0 = (blockIdx.x & 7) << 6;

    const float4 z4 = make_float4(0.f, 0.f, 0.f, 0.f);
    for (int i = tid; i < 256*TWP/4; i += 256) reinterpret_cast<float4*>(Ws)[i] = z4;
    if (tid < 64) idxs[tid] = titems[b*NT_ + t0 + tid];
    __syncthreads();

    for (int i = tid; i < 60*64; i += 256) {
        const int j = i % 60, kq = i / 60;
        float4 w = *reinterpret_cast<const float4*>(Atw + j*EMB_ + 4*kq);
        Ws[(4*kq+0)*TWP + j] = w.x;
        Ws[(4*kq+1)*TWP + j] = w.y;
        Ws[(4*kq+2)*TWP + j] = w.z;
        Ws[(4*kq+3)*TWP + j] = w.w;
    }
    for (int i = tid; i < 64*64; i += 256) {
        const int r = i >> 6, seg = i & 63;
        float4 v = *reinterpret_cast<const float4*>(tvec + (size_t)idxs[r]*EMB_ + 4*seg);
        *reinterpret_cast<float4*>(&Xs[r*CXP + 4*seg]) = v;
    }
    __syncthreads();

    const int tx = tid & 15, ty = tid >> 4;
    float acc[4][4];
    #pragma unroll
    for (int i = 0; i < 4; i++)
        #pragma unroll
        for (int j = 0; j < 4; j++) acc[i][j] = 0.f;

    const float* xr0 = &Xs[(4*ty+0)*CXP];
    const float* xr1 = &Xs[(4*ty+1)*CXP];
    const float* xr2 = &Xs[(4*ty+2)*CXP];
    const float* xr3 = &Xs[(4*ty+3)*CXP];

    #pragma unroll 4
    for (int k = 0; k < 256; k++) {
        float aa[4];
        aa[0] = xr0[k]; aa[1] = xr1[k]; aa[2] = xr2[k]; aa[3] = xr3[k];
        float4 b0 = *reinterpret_cast<const float4*>(&Ws[k*TWP + 4*tx]);
        float bb[4] = {b0.x, b0.y, b0.z, b0.w};
        #pragma unroll
        for (int i = 0; i < 4; i++)
            #pragma unroll
            for (int j = 0; j < 4; j++) acc[i][j] += aa[i]*bb[j];
    }

    float bj[4];
    #pragma unroll
    for (int j = 0; j < 4; j++) {
        const int jj = 4*tx + j;
        bj[j] = (jj < 60) ? Atb[jj] : 0.f;
    }
    __syncthreads();
    #pragma unroll
    for (int i = 0; i < 4; i++) {
        float4 o0 = make_float4(acc[i][0]+bj[0], acc[i][1]+bj[1], acc[i][2]+bj[2], acc[i][3]+bj[3]);
        *reinterpret_cast<float4*>(&Os[(4*ty+i)*TOP + 4*tx]) = o0;
    }
    __syncthreads();

    {
        const int r = tid >> 2, q = tid & 3;
        float ss = 0.f;
        #pragma unroll
        for (int s4 = 0; s4 < 4; s4++) {
            float4 v = *reinterpret_cast<const float4*>(&Os[r*TOP + q*16 + 4*s4]);
            ss += v.x*v.x + v.y*v.y + v.z*v.z + v.w*v.w;
        }
        ss += __shfl_xor_sync(0xffffffffu, ss, 1);
        ss += __shfl_xor_sync(0xffffffffu, ss, 2);
        const float qn = sqrtf(ss);
        if (q == 0) {
            g_qn[b*NT_ + t0 + r] = qn;
            nrm[r] = (qn > 0.f) ? 1.f/qn : 0.f;
        }
    }
    __syncthreads();

    for (int i = tid; i < 64*16; i += 256) {
        const int r = i >> 4, seg = i & 15;
        float4 v = *reinterpret_cast<const float4*>(&Os[r*TOP + 4*seg]);
        const float rn = nrm[r];
        v.x *= rn; v.y *= rn; v.z *= rn; v.w *= rn;
        *reinterpret_cast<float4*>(&g_Q[((size_t)b*NT_ + t0 + r)*DP_ + 4*seg]) = v;
    }
}

// ====================== fused attention + out-projection ===================
#define AQP 68
#define ATT_SMEM_BYTES ((4*64*AQP + 64*256 + 64 + 64 + 64 + 256) * 4)

__global__ void __launch_bounds__(256, 1)
attn_kernel(const float* __restrict__ pos_bias, const float* __restrict__ Rw,
            const float* __restrict__ Rb, float* __restrict__ out)
{
    extern __shared__ float sma[];
    float* Qs  = sma;                 // [64 t][AQP]
    float* Ks  = Qs + 64*AQP;         // [64 d][AQP] (c inner)
    float* Vs  = Ks + 64*AQP;         // [64 c][AQP] (d inner)
    float* Ps  = Vs + 64*AQP;         // [64 t][AQP] scores/probs/out
    float* Rs  = Ps + 64*AQP;         // [64 c][256 e]
    float* qn6 = Rs + 64*256;         // [64]
    float* kns = qn6 + 64;            // [64]
    float* pbs = kns + 64;            // [64]
    float* rbs = pbs + 64;            // [256]

    const int tid = threadIdx.x;
    const int b  = blockIdx.x >> 3;
    const int t0 = (blockIdx.x & 7) << 6;

    const float4 z4 = make_float4(0.f, 0.f, 0.f, 0.f);
    for (int i = tid; i < 64*256/4; i += 256) reinterpret_cast<float4*>(Rs)[i] = z4;
    for (int i = tid; i < 64*16; i += 256) {
        const int r = i >> 4, seg = i & 15;
        *reinterpret_cast<float4*>(&Qs[r*AQP + 4*seg]) =
            *reinterpret_cast<const float4*>(g_Q + ((size_t)b*NT_ + t0 + r)*DP_ + 4*seg);
    }
    if (tid < 64) qn6[tid] = g_qn[b*NT_ + t0 + tid] * 1e6f;
    rbs[tid] = Rb[tid];
    __syncthreads();
    // transpose-load R_w into Rs[c][e] (rows 60..63 stay zero)
    for (int i = tid; i < 256*15; i += 256) {
        const int e = i & 255, cq = i >> 8;
        float4 w = *reinterpret_cast<const float4*>(Rw + e*DKV_ + 4*cq);
        Rs[(4*cq+0)*256 + e] = w.x;
        Rs[(4*cq+1)*256 + e] = w.y;
        Rs[(4*cq+2)*256 + e] = w.z;
        Rs[(4*cq+3)*256 + e] = w.w;
    }

    const int tx = tid & 15, ty = tid >> 4;
    const int rp = tid >> 2, qp = tid & 3;

    float accO[16];
    #pragma unroll
    for (int i = 0; i < 16; i++) accO[i] = 0.f;
    float m = -1e30f, l = 0.f;

    for (int ct = 0; ct < 8; ct++) {
        const int c0 = ct << 6;
        __syncthreads();   // previous PV done: Vs/Ps reusable (also fences Rs fill)
        for (int i = tid; i < 64*16; i += 256) {
            const int d = i >> 4, seg = i & 15;
            *reinterpret_cast<float4*>(&Ks[d*AQP + 4*seg]) =
                *reinterpret_cast<const float4*>(g_K + ((size_t)b*DP_ + d)*NC_ + c0 + 4*seg);
        }
        for (int i = tid; i < 64*16; i += 256) {
            const int c = i >> 4, seg = i & 15;
            *reinterpret_cast<float4*>(&Vs[c*AQP + 4*seg]) =
                *reinterpret_cast<const float4*>(g_V + ((size_t)b*NC_ + c0 + c)*DP_ + 4*seg);
        }
        if (tid < 64) {
            kns[tid] = g_kn[b*NC_ + c0 + tid];
            pbs[tid] = pos_bias[c0 + tid];
        }
        __syncthreads();

        // ---- scores: s[tr][tc] = q-hat . k-hat ----
        float s[4][4];
        #pragma unroll
        for (int i = 0; i < 4; i++)
            #pragma unroll
            for (int j = 0; j < 4; j++) s[i][j] = 0.f;

        const float* q0 = &Qs[(4*ty+0)*AQP];
        const float* q1 = &Qs[(4*ty+1)*AQP];
        const float* q2 = &Qs[(4*ty+2)*AQP];
        const float* q3 = &Qs[(4*ty+3)*AQP];
        #pragma unroll 4
        for (int d = 0; d < 64; d++) {
            float aa[4];
            aa[0] = q0[d]; aa[1] = q1[d]; aa[2] = q2[d]; aa[3] = q3[d];
            float4 b4 = *reinterpret_cast<const float4*>(&Ks[d*AQP + 4*tx]);
            float bb[4] = {b4.x, b4.y, b4.z, b4.w};
            #pragma unroll
            for (int i = 0; i < 4; i++)
                #pragma unroll
                for (int j = 0; j < 4; j++) s[i][j] += aa[i]*bb[j];
        }
        // epsilon factor + positional bias, write to Ps
        {
            float knv[4], pbv[4];
            #pragma unroll
            for (int j = 0; j < 4; j++) { knv[j] = kns[4*tx+j]; pbv[j] = pbs[4*tx+j]; }
            #pragma unroll
            for (int i = 0; i < 4; i++) {
                const float qn = qn6[4*ty+i];
                float4 r4;
                r4.x = s[i][0]*fminf(1.f, qn*knv[0]) + pbv[0];
                r4.y = s[i][1]*fminf(1.f, qn*knv[1]) + pbv[1];
                r4.z = s[i][2]*fminf(1.f, qn*knv[2]) + pbv[2];
                r4.w = s[i][3]*fminf(1.f, qn*knv[3]) + pbv[3];
                *reinterpret_cast<float4*>(&Ps[(4*ty+i)*AQP + 4*tx]) = r4;
            }
        }
        __syncthreads();

        // ---- online softmax (4 threads per row, redundant via shfl) ----
        {
            float vv[16];
            #pragma unroll
            for (int s4 = 0; s4 < 4; s4++) {
                float4 t4 = *reinterpret_cast<const float4*>(&Ps[rp*AQP + qp*16 + 4*s4]);
                vv[4*s4+0] = t4.x; vv[4*s4+1] = t4.y; vv[4*s4+2] = t4.z; vv[4*s4+3] = t4.w;
            }
            float tm = vv[0];
            #pragma unroll
            for (int i = 1; i < 16; i++) tm = fmaxf(tm, vv[i]);
            tm = fmaxf(tm, __shfl_xor_sync(0xffffffffu, tm, 1));
            tm = fmaxf(tm, __shfl_xor_sync(0xffffffffu, tm, 2));
            const float mnew = fmaxf(m, tm);
            const float corr = __expf(m - mnew);
            float lsum = 0.f;
            #pragma unroll
            for (int i = 0; i < 16; i++) { vv[i] = __expf(vv[i] - mnew); lsum += vv[i]; }
            #pragma unroll
            for (int s4 = 0; s4 < 4; s4++) {
                *reinterpret_cast<float4*>(&Ps[rp*AQP + qp*16 + 4*s4]) =
                    make_float4(vv[4*s4+0], vv[4*s4+1], vv[4*s4+2], vv[4*s4+3]);
            }
            lsum += __shfl_xor_sync(0xffffffffu, lsum, 1);
            lsum += __shfl_xor_sync(0xffffffffu, lsum, 2);
            l = l*corr + lsum;
            m = mnew;
            #pragma unroll
            for (int i = 0; i < 16; i++) accO[i] *= corr;
        }
        __syncthreads();

        // ---- PV accumulate: thread (rp, qp) owns row rp, dv cols [16qp,16qp+16) ----
        {
            const float* prow = &Ps[rp*AQP];
            #pragma unroll 2
            for (int c = 0; c < 64; c++) {
                const float p = prow[c];
                const float* vb = &Vs[c*AQP + qp*16];
                float4 v0 = *reinterpret_cast<const float4*>(vb + 0);
                float4 v1 = *reinterpret_cast<const float4*>(vb + 4);
                float4 v2 = *reinterpret_cast<const float4*>(vb + 8);
                float4 v3 = *reinterpret_cast<const float4*>(vb + 12);
                accO[0]  += p*v0.x; accO[1]  += p*v0.y; accO[2]  += p*v0.z; accO[3]  += p*v0.w;
                accO[4]  += p*v1.x; accO[5]  += p*v1.y; accO[6]  += p*v1.z; accO[7]  += p*v1.w;
                accO[8]  += p*v2.x; accO[9]  += p*v2.y; accO[10] += p*v2.z; accO[11] += p*v2.w;
                accO[12] += p*v3.x; accO[13] += p*v3.y; accO[14] += p*v3.z; accO[15] += p*v3.w;
            }
        }
    }

    // ---- finalize: O = acc/l into Ps, then Y = O @ Rs + Rb ----
    const float rl = 1.f / l;
    __syncthreads();
    #pragma unroll
    for (int s4 = 0; s4 < 4; s4++) {
        *reinterpret_cast<float4*>(&Ps[rp*AQP + qp*16 + 4*s4]) =
            make_float4(accO[4*s4+0]*rl, accO[4*s4+1]*rl, accO[4*s4+2]*rl, accO[4*s4+3]*rl);
    }
    __syncthreads();

    #pragma unroll 1
    for (int pass = 0; pass < 4; pass++) {
        float a2[4][4];
        #pragma unroll
        for (int i = 0; i < 4; i++)
            #pragma unroll
            for (int j = 0; j < 4; j++) a2[i][j] = 0.f;

        const float* o0 = &Ps[(4*ty+0)*AQP];
        const float* o1 = &Ps[(4*ty+1)*AQP];
        const float* o2 = &Ps[(4*ty+2)*AQP];
        const float* o3 = &Ps[(4*ty+3)*AQP];
        #pragma unroll 4
        for (int c = 0; c < 64; c++) {
            float aa[4];
            aa[0] = o0[c]; aa[1] = o1[c]; aa[2] = o2[c]; aa[3] = o3[c];
            float4 b4 = *reinterpret_cast<const float4*>(&Rs[c*256 + pass*64 + 4*tx]);
            float bb[4] = {b4.x, b4.y, b4.z, b4.w};
            #pragma unroll
            for (int i = 0; i < 4; i++)
                #pragma unroll
                for (int j = 0; j < 4; j++) a2[i][j] += aa[i]*bb[j];
        }
        const int e0 = pass*64 + 4*tx;
        #pragma unroll
        for (int i = 0; i < 4; i++) {
            float4 y = make_float4(a2[i][0]+rbs[e0+0], a2[i][1]+rbs[e0+1],
                                   a2[i][2]+rbs[e0+2], a2[i][3]+rbs[e0+3]);
            *reinterpret_cast<float4*>(&out[((size_t)(b*NT_ + t0 + 4*ty + i))*EMB_ + e0]) = y;
        }
    }
}

// ================================ launch ===================================
extern "C" void kernel_launch(void* const* d_in, const int* in_sizes, int n_in,
                              void* d_out, int out_size)
{
    const int*   titems = (const int*)  d_in[0];
    const int*   citems = (const int*)  d_in[1];
    const float* tvec   = (const float*)d_in[2];
    const float* cvec   = (const float*)d_in[3];
    const float* Atw    = (const float*)d_in[4];
    const float* Atb    = (const float*)d_in[5];
    const float* Acw    = (const float*)d_in[6];
    const float* Acb    = (const float*)d_in[7];
    const float* Bcw    = (const float*)d_in[8];
    const float* Bcb    = (const float*)d_in[9];
    const float* posb   = (const float*)d_in[10];
    const float* Rw     = (const float*)d_in[11];
    const float* Rb     = (const float*)d_in[12];
    float* out = (float*)d_out;

    cudaFuncSetAttribute(proj_ctx_kernel, cudaFuncAttributeMaxDynamicSharedMemorySize, CTX_SMEM_BYTES);
    cudaFuncSetAttribute(proj_tgt_kernel, cudaFuncAttributeMaxDynamicSharedMemorySize, TGT_SMEM_BYTES);
    cudaFuncSetAttribute(attn_kernel,     cudaFuncAttributeMaxDynamicSharedMemorySize, ATT_SMEM_BYTES);

    proj_ctx_kernel<<<B_*8, 256, CTX_SMEM_BYTES>>>(citems, cvec, Acw, Acb, Bcw, Bcb);
    proj_tgt_kernel<<<B_*8, 256, TGT_SMEM_BYTES>>>(titems, tvec, Atw, Atb);
    attn_kernel<<<B_*8, 256, ATT_SMEM_BYTES>>>(posb, Rw, Rb, out);
}

// round 3
// speedup vs baseline: 2.3963x; 2.3963x over previous
#include <cuda_runtime.h>

#define B_   128
#define NT_  512
#define NC_  512
#define EMB_ 256
#define DKV_ 60
#define DP_  64

typedef unsigned long long ull;

__device__ __forceinline__ ull dup2(float x) {
    ull r; asm("mov.b64 %0, {%1, %1};" : "=l"(r) : "f"(x)); return r;
}
__device__ __forceinline__ void upk2(ull v, float& lo, float& hi) {
    asm("mov.b64 {%0, %1}, %2;" : "=f"(lo), "=f"(hi) : "l"(v));
}
__device__ __forceinline__ ull ffma2(ull a, ull b, ull c) {
    ull d; asm("fma.rn.f32x2 %0, %1, %2, %3;" : "=l"(d) : "l"(a), "l"(b), "l"(c)); return d;
}

// ---------------- scratch ----------------
__device__ float g_Q[B_*DP_*NT_];   // (b, d, t) d-major, pre-normalized q-hat
__device__ float g_K[B_*DP_*NC_];   // (b, d, c) d-major, pre-normalized k-hat
__device__ float g_V[B_*NC_*DP_];   // (b, c, d) row-major
__device__ float g_qn[B_*NT_];
__device__ float g_kn[B_*NC_];
__device__ float g_Wc[256*128];     // [k][j]: j<60 Ac, 64..123 Bc, else 0
__device__ float g_Wq[256*64];      // [k][j]: j<60 At else 0
__device__ float g_Rt[64*256];      // [c][e]: c<60 Rw[e][c] else 0

// ============================ weight prep ==================================
__global__ void prep_kernel(const float* __restrict__ Atw, const float* __restrict__ Acw,
                            const float* __restrict__ Bcw, const float* __restrict__ Rw)
{
    const int blk = blockIdx.x, tid = threadIdx.x;
    if (blk < 256) {
        const int k = blk;
        if (tid < 128) {
            const int j = tid;
            float v = 0.f;
            if (j < 60) v = Acw[j*EMB_ + k];
            else if (j >= 64 && j < 124) v = Bcw[(j-64)*EMB_ + k];
            g_Wc[k*128 + j] = v;
        } else {
            const int j = tid - 128;
            if (j < 64) g_Wq[k*64 + j] = (j < 60) ? Atw[j*EMB_ + k] : 0.f;
        }
    } else {
        const int c = blk - 256;            // 0..63
        g_Rt[c*256 + tid] = (c < 60) ? Rw[tid*DKV_ + c] : 0.f;
    }
}

// ===================== context projection (K,V) ============================
// CTA: (b, 128 ctx rows). 256 threads (16x16). Thread tile 8 rows x 8 cols.
#define PXP 132
#define CTX_SMEM_BYTES ((64*PXP + 64*PXP + 128) * 4)

__global__ void __launch_bounds__(256)
proj_ctx_kernel(const int* __restrict__ citems, const float* __restrict__ cvec,
                const float* __restrict__ Acb, const float* __restrict__ Bcb)
{
    extern __shared__ float smc[];
    float* Xt = smc;               // [64 k][PXP rows]
    float* Ws = smc + 64*PXP;      // [64 k][PXP cols(128)]
    int*  idxs = (int*)(Ws + 64*PXP);

    const int tid = threadIdx.x;
    const int tx = tid & 15, ty = tid >> 4;
    const int b  = blockIdx.x >> 2;
    const int c0 = (blockIdx.x & 3) << 7;

    if (tid < 128) idxs[tid] = citems[b*NC_ + c0 + tid];
    __syncthreads();

    ull acc2[8][4];
    #pragma unroll
    for (int i = 0; i < 8; i++)
        #pragma unroll
        for (int j = 0; j < 4; j++) acc2[i][j] = 0ULL;

    for (int kc = 0; kc < 4; kc++) {
        __syncthreads();
        // Xt fill (gather, transposed)
        for (int i = tid; i < 2048; i += 256) {
            const int r = i >> 4, s = i & 15;
            float4 v = *reinterpret_cast<const float4*>(cvec + (size_t)idxs[r]*EMB_ + kc*64 + 4*s);
            Xt[(4*s+0)*PXP + r] = v.x;
            Xt[(4*s+1)*PXP + r] = v.y;
            Xt[(4*s+2)*PXP + r] = v.z;
            Xt[(4*s+3)*PXP + r] = v.w;
        }
        // Ws fill (coalesced)
        for (int i = tid; i < 2048; i += 256) {
            const int kk = i >> 5, s = i & 31;
            *reinterpret_cast<float4*>(&Ws[kk*PXP + 4*s]) =
                *reinterpret_cast<const float4*>(&g_Wc[(kc*64 + kk)*128 + 4*s]);
        }
        __syncthreads();

        #pragma unroll 4
        for (int kk = 0; kk < 64; kk++) {
            float4 a0 = *reinterpret_cast<const float4*>(&Xt[kk*PXP + 8*ty]);
            float4 a1 = *reinterpret_cast<const float4*>(&Xt[kk*PXP + 8*ty + 4]);
            ulonglong2 b0 = *reinterpret_cast<const ulonglong2*>(&Ws[kk*PXP + 8*tx]);
            ulonglong2 b1 = *reinterpret_cast<const ulonglong2*>(&Ws[kk*PXP + 8*tx + 4]);
            ull ad[8];
            ad[0]=dup2(a0.x); ad[1]=dup2(a0.y); ad[2]=dup2(a0.z); ad[3]=dup2(a0.w);
            ad[4]=dup2(a1.x); ad[5]=dup2(a1.y); ad[6]=dup2(a1.z); ad[7]=dup2(a1.w);
            #pragma unroll
            for (int i = 0; i < 8; i++) {
                acc2[i][0] = ffma2(ad[i], b0.x, acc2[i][0]);
                acc2[i][1] = ffma2(ad[i], b0.y, acc2[i][1]);
                acc2[i][2] = ffma2(ad[i], b1.x, acc2[i][2]);
                acc2[i][3] = ffma2(ad[i], b1.y, acc2[i][3]);
            }
        }
    }

    // unpack + bias
    float o[8][8];
    #pragma unroll
    for (int i = 0; i < 8; i++)
        #pragma unroll
        for (int jp = 0; jp < 4; jp++) upk2(acc2[i][jp], o[i][2*jp], o[i][2*jp+1]);

    float bj[8];
    #pragma unroll
    for (int j = 0; j < 8; j++) {
        if (tx < 8) { const int jj = 8*tx + j;      bj[j] = (jj < 60) ? Acb[jj] : 0.f; }
        else        { const int jj = 8*(tx-8) + j;  bj[j] = (jj < 60) ? Bcb[jj] : 0.f; }
    }
    #pragma unroll
    for (int i = 0; i < 8; i++)
        #pragma unroll
        for (int j = 0; j < 8; j++) o[i][j] += bj[j];

    // row sums of squares (meaningful for K threads tx<8); converged shfl
    float ss[8];
    #pragma unroll
    for (int i = 0; i < 8; i++) {
        float s = 0.f;
        #pragma unroll
        for (int j = 0; j < 8; j++) s += o[i][j]*o[i][j];
        ss[i] = s;
    }
    #pragma unroll
    for (int i = 0; i < 8; i++) {
        ss[i] += __shfl_xor_sync(0xffffffffu, ss[i], 1);
        ss[i] += __shfl_xor_sync(0xffffffffu, ss[i], 2);
        ss[i] += __shfl_xor_sync(0xffffffffu, ss[i], 4);
    }

    if (tx < 8) {
        float inv[8];
        #pragma unroll
        for (int i = 0; i < 8; i++) {
            const float kn = sqrtf(ss[i]);
            inv[i] = (kn > 0.f) ? 1.f/kn : 0.f;
            if (tx == 0) g_kn[b*NC_ + c0 + 8*ty + i] = kn;
        }
        #pragma unroll
        for (int j = 0; j < 8; j++) {
            float* dst = g_K + ((size_t)b*DP_ + 8*tx + j)*NC_ + c0 + 8*ty;
            #pragma unroll
            for (int i = 0; i < 8; i++) dst[i] = o[i][j]*inv[i];
        }
    } else {
        #pragma unroll
        for (int i = 0; i < 8; i++) {
            float* dst = g_V + ((size_t)b*NC_ + c0 + 8*ty + i)*DP_ + 8*(tx-8);
            *reinterpret_cast<float4*>(dst)     = make_float4(o[i][0], o[i][1], o[i][2], o[i][3]);
            *reinterpret_cast<float4*>(dst + 4) = make_float4(o[i][4], o[i][5], o[i][6], o[i][7]);
        }
    }
}

// ========================= target projection (Q) ===========================
// CTA: (b, 128 t rows). 256 threads. Thread tile 8 rows x 4 cols.
#define TGT_SMEM_BYTES ((64*PXP + 64*68 + 128) * 4)

__global__ void __launch_bounds__(256)
proj_tgt_kernel(const int* __restrict__ titems, const float* __restrict__ tvec,
                const float* __restrict__ Atb)
{
    extern __shared__ float smt[];
    float* Xt = smt;               // [64 k][PXP rows]
    float* Ws = smt + 64*PXP;      // [64 k][68 cols(64)]
    int*  idxs = (int*)(Ws + 64*68);

    const int tid = threadIdx.x;
    const int tx = tid & 15, ty = tid >> 4;
    const int b  = blockIdx.x >> 2;
    const int t0 = (blockIdx.x & 3) << 7;

    if (tid < 128) idxs[tid] = titems[b*NT_ + t0 + tid];
    __syncthreads();

    ull acc2[8][2];
    #pragma unroll
    for (int i = 0; i < 8; i++) { acc2[i][0] = 0ULL; acc2[i][1] = 0ULL; }

    for (int kc = 0; kc < 4; kc++) {
        __syncthreads();
        for (int i = tid; i < 2048; i += 256) {
            const int r = i >> 4, s = i & 15;
            float4 v = *reinterpret_cast<const float4*>(tvec + (size_t)idxs[r]*EMB_ + kc*64 + 4*s);
            Xt[(4*s+0)*PXP + r] = v.x;
            Xt[(4*s+1)*PXP + r] = v.y;
            Xt[(4*s+2)*PXP + r] = v.z;
            Xt[(4*s+3)*PXP + r] = v.w;
        }
        for (int i = tid; i < 1024; i += 256) {
            const int kk = i >> 4, s = i & 15;
            *reinterpret_cast<float4*>(&Ws[kk*68 + 4*s]) =
                *reinterpret_cast<const float4*>(&g_Wq[(kc*64 + kk)*64 + 4*s]);
        }
        __syncthreads();

        #pragma unroll 4
        for (int kk = 0; kk < 64; kk++) {
            float4 a0 = *reinterpret_cast<const float4*>(&Xt[kk*PXP + 8*ty]);
            float4 a1 = *reinterpret_cast<const float4*>(&Xt[kk*PXP + 8*ty + 4]);
            ulonglong2 b0 = *reinterpret_cast<const ulonglong2*>(&Ws[kk*68 + 4*tx]);
            ull ad[8];
            ad[0]=dup2(a0.x); ad[1]=dup2(a0.y); ad[2]=dup2(a0.z); ad[3]=dup2(a0.w);
            ad[4]=dup2(a1.x); ad[5]=dup2(a1.y); ad[6]=dup2(a1.z); ad[7]=dup2(a1.w);
            #pragma unroll
            for (int i = 0; i < 8; i++) {
                acc2[i][0] = ffma2(ad[i], b0.x, acc2[i][0]);
                acc2[i][1] = ffma2(ad[i], b0.y, acc2[i][1]);
            }
        }
    }

    float o[8][4];
    #pragma unroll
    for (int i = 0; i < 8; i++) {
        upk2(acc2[i][0], o[i][0], o[i][1]);
        upk2(acc2[i][1], o[i][2], o[i][3]);
    }
    float bj[4];
    #pragma unroll
    for (int j = 0; j < 4; j++) { const int jj = 4*tx + j; bj[j] = (jj < 60) ? Atb[jj] : 0.f; }
    #pragma unroll
    for (int i = 0; i < 8; i++)
        #pragma unroll
        for (int j = 0; j < 4; j++) o[i][j] += bj[j];

    float ss[8];
    #pragma unroll
    for (int i = 0; i < 8; i++) {
        float s = 0.f;
        #pragma unroll
        for (int j = 0; j < 4; j++) s += o[i][j]*o[i][j];
        ss[i] = s;
    }
    #pragma unroll
    for (int i = 0; i < 8; i++) {
        ss[i] += __shfl_xor_sync(0xffffffffu, ss[i], 1);
        ss[i] += __shfl_xor_sync(0xffffffffu, ss[i], 2);
        ss[i] += __shfl_xor_sync(0xffffffffu, ss[i], 4);
        ss[i] += __shfl_xor_sync(0xffffffffu, ss[i], 8);
    }

    float inv[8];
    #pragma unroll
    for (int i = 0; i < 8; i++) {
        const float qn = sqrtf(ss[i]);
        inv[i] = (qn > 0.f) ? 1.f/qn : 0.f;
        if (tx == 0) g_qn[b*NT_ + t0 + 8*ty + i] = qn;
    }
    #pragma unroll
    for (int j = 0; j < 4; j++) {
        float* dst = g_Q + ((size_t)b*DP_ + 4*tx + j)*NT_ + t0 + 8*ty;
        #pragma unroll
        for (int i = 0; i < 8; i++) dst[i] = o[i][j]*inv[i];
    }
}

// ====================== fused attention + out-projection ===================
// CTA: (b, 64 t rows). 256 threads (16x16). Thread tile 4x4 in all GEMMs.
#define AQP 68
#define ATT_SMEM_BYTES ((4*64*AQP + 64*5) * 4)

__global__ void __launch_bounds__(256)
attn_kernel(const float* __restrict__ pos_bias, const float* __restrict__ Rb,
            float* __restrict__ out)
{
    extern __shared__ float sma[];
    float* Qt  = sma;                 // [64 d][AQP t]
    float* Ks  = Qt + 64*AQP;         // [64 d][AQP c]  (reused as Rs in epilogue)
    float* Vs  = Ks + 64*AQP;         // [64 c][AQP d]
    float* Pt  = Vs + 64*AQP;         // [64 c][AQP t]  (reused as Ot [d][t])
    float* qn6 = Pt + 64*AQP;         // [64]
    float* kns = qn6 + 64;            // [64]
    float* pbs = kns + 64;            // [64]
    float* cor = pbs + 64;            // [64]
    float* ivl = cor + 64;            // [64]
    float* Rs = Ks;
    float* Ot = Pt;

    const int tid = threadIdx.x;
    const int tx = tid & 15, ty = tid >> 4;
    const int rp = tid >> 2, qp = tid & 3;
    const int b  = blockIdx.x >> 3;
    const int t0 = (blockIdx.x & 7) << 6;

    for (int i = tid; i < 1024; i += 256) {
        const int d = i >> 4, s = i & 15;
        *reinterpret_cast<float4*>(&Qt[d*AQP + 4*s]) =
            *reinterpret_cast<const float4*>(g_Q + ((size_t)b*DP_ + d)*NT_ + t0 + 4*s);
    }
    if (tid < 64) qn6[tid] = g_qn[b*NT_ + t0 + tid] * 1e6f;

    ull accO[4][2];
    #pragma unroll
    for (int i = 0; i < 4; i++) { accO[i][0] = 0ULL; accO[i][1] = 0ULL; }
    float m = -1e30f, l = 0.f;

    for (int ct = 0; ct < 8; ct++) {
        const int c0 = ct << 6;
        __syncthreads();
        for (int i = tid; i < 1024; i += 256) {
            const int d = i >> 4, s = i & 15;
            *reinterpret_cast<float4*>(&Ks[d*AQP + 4*s]) =
                *reinterpret_cast<const float4*>(g_K + ((size_t)b*DP_ + d)*NC_ + c0 + 4*s);
        }
        for (int i = tid; i < 1024; i += 256) {
            const int c = i >> 4, s = i & 15;
            *reinterpret_cast<float4*>(&Vs[c*AQP + 4*s]) =
                *reinterpret_cast<const float4*>(g_V + ((size_t)b*NC_ + c0 + c)*DP_ + 4*s);
        }
        if (tid < 64) {
            kns[tid] = g_kn[b*NC_ + c0 + tid];
            pbs[tid] = pos_bias[c0 + tid];
        }
        __syncthreads();

        // ---- scores: 4 t x 4 c per thread ----
        ull s2[4][2];
        #pragma unroll
        for (int i = 0; i < 4; i++) { s2[i][0] = 0ULL; s2[i][1] = 0ULL; }
        #pragma unroll 4
        for (int d = 0; d < 64; d++) {
            float4 av = *reinterpret_cast<const float4*>(&Qt[d*AQP + 4*ty]);
            ulonglong2 bv = *reinterpret_cast<const ulonglong2*>(&Ks[d*AQP + 4*tx]);
            ull a0 = dup2(av.x), a1 = dup2(av.y), a2 = dup2(av.z), a3 = dup2(av.w);
            s2[0][0]=ffma2(a0,bv.x,s2[0][0]); s2[0][1]=ffma2(a0,bv.y,s2[0][1]);
            s2[1][0]=ffma2(a1,bv.x,s2[1][0]); s2[1][1]=ffma2(a1,bv.y,s2[1][1]);
            s2[2][0]=ffma2(a2,bv.x,s2[2][0]); s2[2][1]=ffma2(a2,bv.y,s2[2][1]);
            s2[3][0]=ffma2(a3,bv.x,s2[3][0]); s2[3][1]=ffma2(a3,bv.y,s2[3][1]);
        }
        float sc[4][4];
        #pragma unroll
        for (int i = 0; i < 4; i++) {
            upk2(s2[i][0], sc[i][0], sc[i][1]);
            upk2(s2[i][1], sc[i][2], sc[i][3]);
        }
        {
            float knv[4], pbv[4], qv[4];
            #pragma unroll
            for (int j = 0; j < 4; j++) { knv[j] = kns[4*tx+j]; pbv[j] = pbs[4*tx+j]; }
            #pragma unroll
            for (int i = 0; i < 4; i++) qv[i] = qn6[4*ty+i];
            #pragma unroll
            for (int j = 0; j < 4; j++) {
                float4 col;
                col.x = sc[0][j]*fminf(1.f, qv[0]*knv[j]) + pbv[j];
                col.y = sc[1][j]*fminf(1.f, qv[1]*knv[j]) + pbv[j];
                col.z = sc[2][j]*fminf(1.f, qv[2]*knv[j]) + pbv[j];
                col.w = sc[3][j]*fminf(1.f, qv[3]*knv[j]) + pbv[j];
                *reinterpret_cast<float4*>(&Pt[(4*tx+j)*AQP + 4*ty]) = col;
            }
        }
        __syncthreads();

        // ---- online softmax: 4 threads per t-row (rp=row, qp=16-col slab) ----
        {
            float vv[16];
            #pragma unroll
            for (int s = 0; s < 16; s++) vv[s] = Pt[(16*qp+s)*AQP + rp];
            float tm = vv[0];
            #pragma unroll
            for (int s = 1; s < 16; s++) tm = fmaxf(tm, vv[s]);
            tm = fmaxf(tm, __shfl_xor_sync(0xffffffffu, tm, 1));
            tm = fmaxf(tm, __shfl_xor_sync(0xffffffffu, tm, 2));
            const float mnew = fmaxf(m, tm);
            const float corr = __expf(m - mnew);
            float lsum = 0.f;
            #pragma unroll
            for (int s = 0; s < 16; s++) { vv[s] = __expf(vv[s] - mnew); lsum += vv[s]; }
            #pragma unroll
            for (int s = 0; s < 16; s++) Pt[(16*qp+s)*AQP + rp] = vv[s];
            lsum += __shfl_xor_sync(0xffffffffu, lsum, 1);
            lsum += __shfl_xor_sync(0xffffffffu, lsum, 2);
            l = l*corr + lsum;
            m = mnew;
            if (qp == 0) cor[rp] = corr;
        }
        __syncthreads();

        // ---- PV: 4 t x 4 d per thread ----
        {
            #pragma unroll
            for (int i = 0; i < 4; i++) {
                const ull c2 = dup2(cor[4*ty+i]);
                accO[i][0] = ffma2(accO[i][0], c2, 0ULL);
                accO[i][1] = ffma2(accO[i][1], c2, 0ULL);
            }
            #pragma unroll 4
            for (int c = 0; c < 64; c++) {
                float4 av = *reinterpret_cast<const float4*>(&Pt[c*AQP + 4*ty]);
                ulonglong2 bv = *reinterpret_cast<const ulonglong2*>(&Vs[c*AQP + 4*tx]);
                ull a0 = dup2(av.x), a1 = dup2(av.y), a2 = dup2(av.z), a3 = dup2(av.w);
                accO[0][0]=ffma2(a0,bv.x,accO[0][0]); accO[0][1]=ffma2(a0,bv.y,accO[0][1]);
                accO[1][0]=ffma2(a1,bv.x,accO[1][0]); accO[1][1]=ffma2(a1,bv.y,accO[1][1]);
                accO[2][0]=ffma2(a2,bv.x,accO[2][0]); accO[2][1]=ffma2(a2,bv.y,accO[2][1]);
                accO[3][0]=ffma2(a3,bv.x,accO[3][0]); accO[3][1]=ffma2(a3,bv.y,accO[3][1]);
            }
        }
    }

    __syncthreads();
    if (qp == 0) ivl[rp] = 1.f / l;
    __syncthreads();

    // write O^T [d][t] into Ot (overlays Pt), scaled by 1/l
    {
        float ov[4][4];
        #pragma unroll
        for (int i = 0; i < 4; i++) {
            upk2(accO[i][0], ov[i][0], ov[i][1]);
            upk2(accO[i][1], ov[i][2], ov[i][3]);
        }
        float il[4];
        #pragma unroll
        for (int i = 0; i < 4; i++) il[i] = ivl[4*ty+i];
        #pragma unroll
        for (int j = 0; j < 4; j++) {
            float4 col = make_float4(ov[0][j]*il[0], ov[1][j]*il[1], ov[2][j]*il[2], ov[3][j]*il[3]);
            *reinterpret_cast<float4*>(&Ot[(4*tx+j)*AQP + 4*ty]) = col;
        }
    }

    // ---- epilogue: Y[t][e] = O[t][d59] @ Rt[d][e] + Rb, 4 passes of 64 e ----
    for (int pass = 0; pass < 4; pass++) {
        __syncthreads();     // Ot writes done (pass0) / prev pass GEMM done
        for (int i = tid; i < 1024; i += 256) {
            const int d = i >> 4, s = i & 15;
            *reinterpret_cast<float4*>(&Rs[d*AQP + 4*s]) =
                *reinterpret_cast<const float4*>(&g_Rt[d*256 + pass*64 + 4*s]);
        }
        __syncthreads();

        ull e2[4][2];
        #pragma unroll
        for (int i = 0; i < 4; i++) { e2[i][0] = 0ULL; e2[i][1] = 0ULL; }
        #pragma unroll 4
        for (int d = 0; d < 64; d++) {
            float4 av = *reinterpret_cast<const float4*>(&Ot[d*AQP + 4*ty]);
            ulonglong2 bv = *reinterpret_cast<const ulonglong2*>(&Rs[d*AQP + 4*tx]);
            ull a0 = dup2(av.x), a1 = dup2(av.y), a2 = dup2(av.z), a3 = dup2(av.w);
            e2[0][0]=ffma2(a0,bv.x,e2[0][0]); e2[0][1]=ffma2(a0,bv.y,e2[0][1]);
            e2[1][0]=ffma2(a1,bv.x,e2[1][0]); e2[1][1]=ffma2(a1,bv.y,e2[1][1]);
            e2[2][0]=ffma2(a2,bv.x,e2[2][0]); e2[2][1]=ffma2(a2,bv.y,e2[2][1]);
            e2[3][0]=ffma2(a3,bv.x,e2[3][0]); e2[3][1]=ffma2(a3,bv.y,e2[3][1]);
        }
        const int e0 = pass*64 + 4*tx;
        float4 rb = *reinterpret_cast<const float4*>(Rb + e0);
        #pragma unroll
        for (int i = 0; i < 4; i++) {
            float y0, y1, y2, y3;
            upk2(e2[i][0], y0, y1);
            upk2(e2[i][1], y2, y3);
            *reinterpret_cast<float4*>(&out[((size_t)(b*NT_ + t0 + 4*ty + i))*EMB_ + e0]) =
                make_float4(y0+rb.x, y1+rb.y, y2+rb.z, y3+rb.w);
        }
    }
}

// ================================ launch ===================================
extern "C" void kernel_launch(void* const* d_in, const int* in_sizes, int n_in,
                              void* d_out, int out_size)
{
    const int*   titems = (const int*)  d_in[0];
    const int*   citems = (const int*)  d_in[1];
    const float* tvec   = (const float*)d_in[2];
    const float* cvec   = (const float*)d_in[3];
    const float* Atw    = (const float*)d_in[4];
    const float* Atb    = (const float*)d_in[5];
    const float* Acw    = (const float*)d_in[6];
    const float* Acb    = (const float*)d_in[7];
    const float* Bcw    = (const float*)d_in[8];
    const float* Bcb    = (const float*)d_in[9];
    const float* posb   = (const float*)d_in[10];
    const float* Rw     = (const float*)d_in[11];
    const float* Rb     = (const float*)d_in[12];
    float* out = (float*)d_out;

    cudaFuncSetAttribute(proj_ctx_kernel, cudaFuncAttributeMaxDynamicSharedMemorySize, CTX_SMEM_BYTES);
    cudaFuncSetAttribute(proj_tgt_kernel, cudaFuncAttributeMaxDynamicSharedMemorySize, TGT_SMEM_BYTES);
    cudaFuncSetAttribute(attn_kernel,     cudaFuncAttributeMaxDynamicSharedMemorySize, ATT_SMEM_BYTES);

    prep_kernel<<<320, 256>>>(Atw, Acw, Bcw, Rw);
    proj_ctx_kernel<<<B_*4, 256, CTX_SMEM_BYTES>>>(citems, cvec, Acb, Bcb);
    proj_tgt_kernel<<<B_*4, 256, TGT_SMEM_BYTES>>>(titems, tvec, Atb);
    attn_kernel<<<B_*8, 256, ATT_SMEM_BYTES>>>(posb, Rb, out);
}